// round 4
// baseline (speedup 1.0000x reference)
#include <cuda_runtime.h>

#define B_  2
#define S_  4096
#define D_  768
#define H_  12
#define HD_ 64
#define M_  (B_ * S_)   // 8192 rows

// Scratch (device globals: no allocation allowed in kernel_launch)
__device__ float g_q[(size_t)B_ * H_ * S_ * HD_];
__device__ float g_k[(size_t)B_ * H_ * S_ * HD_];
__device__ float g_v[(size_t)B_ * H_ * S_ * HD_];
__device__ float g_ctx[(size_t)B_ * S_ * D_];

// ---------------------------------------------------------------------------
// GEMM: C = A[M,K] @ W[N,K]^T   (i.e. C[m][n] = sum_k A[m,k] * W[n,k])
// MODE 0: scatter to [B,H,S,HD] layout (QKV projections)
// MODE 1: write [M,N] row-major + bias (output projection)
// Tile 64x64, BK=16, 256 threads, 4x4 per-thread microtile.
// ---------------------------------------------------------------------------
template <int MODE>
__global__ __launch_bounds__(256)
void gemm_kernel(const float* __restrict__ A, const float* __restrict__ W,
                 const float* __restrict__ bias, float* __restrict__ C,
                 int Kdim, int Ndim)
{
    __shared__ float At[16][64];   // k-major A tile
    __shared__ float Bt[16][64];   // k-major W tile

    const int tid = threadIdx.x;
    const int tx = tid & 15;
    const int ty = tid >> 4;
    const int m0 = blockIdx.y * 64;
    const int n0 = blockIdx.x * 64;

    const int lr = tid >> 2;         // 0..63 : row within tile being loaded
    const int lc = (tid & 3) * 4;    // 0,4,8,12 : k-column within BK chunk

    float acc[4][4] = {};

    for (int k0 = 0; k0 < Kdim; k0 += 16) {
        float4 a = *(const float4*)(A + (size_t)(m0 + lr) * Kdim + k0 + lc);
        float4 b = *(const float4*)(W + (size_t)(n0 + lr) * Kdim + k0 + lc);
        __syncthreads();   // protect previous iteration's smem reads
        At[lc + 0][lr] = a.x; At[lc + 1][lr] = a.y;
        At[lc + 2][lr] = a.z; At[lc + 3][lr] = a.w;
        Bt[lc + 0][lr] = b.x; Bt[lc + 1][lr] = b.y;
        Bt[lc + 2][lr] = b.z; Bt[lc + 3][lr] = b.w;
        __syncthreads();

        #pragma unroll
        for (int kk = 0; kk < 16; kk++) {
            float4 av = *(const float4*)&At[kk][ty * 4];
            float4 bv = *(const float4*)&Bt[kk][tx * 4];
            float ar[4] = {av.x, av.y, av.z, av.w};
            float br[4] = {bv.x, bv.y, bv.z, bv.w};
            #pragma unroll
            for (int i = 0; i < 4; i++)
                #pragma unroll
                for (int j = 0; j < 4; j++)
                    acc[i][j] += ar[i] * br[j];
        }
    }

    if (MODE == 0) {
        // n-tile (64 wide) == exactly one head; hd = tx*4 .. tx*4+3 contiguous
        const int h  = n0 >> 6;
        const int hd = tx * 4;
        #pragma unroll
        for (int i = 0; i < 4; i++) {
            int m = m0 + ty * 4 + i;
            int b = m / S_, s = m - b * S_;
            float4 o = make_float4(acc[i][0], acc[i][1], acc[i][2], acc[i][3]);
            *(float4*)(C + (((size_t)(b * H_ + h) * S_ + s) << 6) + hd) = o;
        }
    } else {
        const int n = n0 + tx * 4;
        float4 bb = *(const float4*)(bias + n);
        #pragma unroll
        for (int i = 0; i < 4; i++) {
            int m = m0 + ty * 4 + i;
            float4 o = make_float4(acc[i][0] + bb.x, acc[i][1] + bb.y,
                                   acc[i][2] + bb.z, acc[i][3] + bb.w);
            *(float4*)(C + (size_t)m * Ndim + n) = o;
        }
    }
}

// ---------------------------------------------------------------------------
// Flash attention (causal), fp32 SIMT.
// One CTA = 64 query rows of one (b,h); iterates KV tiles 0..qt.
// Online softmax; row stats replicated across the 16 lanes of each row group
// via shuffle reductions (lanes of a warp = {ty, ty^1} x tx[0..15]).
// smem (dynamic, 65792 B): Qt[64][64] k-major, Kt[64][64] k-major,
//                          Vs[64][64] row-major, Pt[64][65] (padded transpose)
// ---------------------------------------------------------------------------
__global__ __launch_bounds__(256, 2)
void flash_kernel(const float* __restrict__ Q, const float* __restrict__ K,
                  const float* __restrict__ V, float* __restrict__ ctx)
{
    extern __shared__ float sm[];
    float* Qt = sm;             // 4096 floats
    float* Kt = sm + 4096;      // 4096
    float* Vs = sm + 8192;      // 4096
    float* Pt = sm + 12288;     // 64 * 65 = 4160

    const int tid = threadIdx.x;
    const int tx  = tid & 15;
    const int ty  = tid >> 4;
    const int qt  = blockIdx.x;          // query tile index (0..63)
    const int bh  = blockIdx.y;          // b*H + h
    const int q0  = qt * 64;

    const float* Qg = Q + ((size_t)bh * S_ + q0) * HD_;
    const float* Kg = K + (size_t)bh * S_ * HD_;
    const float* Vg = V + (size_t)bh * S_ * HD_;

    // ---- load Q tile, transposed to k-major ----
    {
        const int r  = tid >> 2;
        const int c0 = (tid & 3) * 4;
        #pragma unroll
        for (int cc = 0; cc < 4; cc++) {
            int c = c0 + cc * 16;
            float4 v = *(const float4*)(Qg + r * HD_ + c);
            Qt[(c + 0) * 64 + r] = v.x;
            Qt[(c + 1) * 64 + r] = v.y;
            Qt[(c + 2) * 64 + r] = v.z;
            Qt[(c + 3) * 64 + r] = v.w;
        }
    }

    float o[4][4] = {};
    float mrow[4] = {-1e30f, -1e30f, -1e30f, -1e30f};
    float lrow[4] = {};

    const float scale = 0.125f;   // 1/sqrt(64)
    const int ntiles = qt + 1;    // causal: only tiles <= qt

    for (int kt = 0; kt < ntiles; kt++) {
        __syncthreads();   // previous tile's Kt/Vs/Pt reads done
        // ---- load K tile (transposed) and V tile ----
        {
            const int r  = tid >> 2;
            const int c0 = (tid & 3) * 4;
            const float* kg = Kg + (size_t)(kt * 64 + r) * HD_;
            const float* vg = Vg + (size_t)(kt * 64 + r) * HD_;
            #pragma unroll
            for (int cc = 0; cc < 4; cc++) {
                int c = c0 + cc * 16;
                float4 kv = *(const float4*)(kg + c);
                Kt[(c + 0) * 64 + r] = kv.x;
                Kt[(c + 1) * 64 + r] = kv.y;
                Kt[(c + 2) * 64 + r] = kv.z;
                Kt[(c + 3) * 64 + r] = kv.w;
                float4 vv = *(const float4*)(vg + c);
                *(float4*)(Vs + r * 64 + c) = vv;
            }
        }
        __syncthreads();

        // ---- S = Q @ K^T (4x4 microtile) ----
        float s[4][4] = {};
        #pragma unroll 16
        for (int kk = 0; kk < 64; kk++) {
            float4 a = *(const float4*)(Qt + kk * 64 + ty * 4);
            float4 b = *(const float4*)(Kt + kk * 64 + tx * 4);
            float ar[4] = {a.x, a.y, a.z, a.w};
            float br[4] = {b.x, b.y, b.z, b.w};
            #pragma unroll
            for (int i = 0; i < 4; i++)
                #pragma unroll
                for (int j = 0; j < 4; j++)
                    s[i][j] += ar[i] * br[j];
        }

        // ---- scale + causal mask (only diagonal tile needs masking) ----
        if (kt == qt) {
            #pragma unroll
            for (int i = 0; i < 4; i++)
                #pragma unroll
                for (int j = 0; j < 4; j++) {
                    int qr = ty * 4 + i, kc = tx * 4 + j;
                    s[i][j] = (kc <= qr) ? s[i][j] * scale : -1e30f;
                }
        } else {
            #pragma unroll
            for (int i = 0; i < 4; i++)
                #pragma unroll
                for (int j = 0; j < 4; j++)
                    s[i][j] *= scale;
        }

        // ---- online softmax (per row-group of 4 rows) ----
        #pragma unroll
        for (int i = 0; i < 4; i++) {
            float mt = fmaxf(fmaxf(s[i][0], s[i][1]), fmaxf(s[i][2], s[i][3]));
            mt = fmaxf(mt, __shfl_xor_sync(0xffffffffu, mt, 8));
            mt = fmaxf(mt, __shfl_xor_sync(0xffffffffu, mt, 4));
            mt = fmaxf(mt, __shfl_xor_sync(0xffffffffu, mt, 2));
            mt = fmaxf(mt, __shfl_xor_sync(0xffffffffu, mt, 1));
            float mnew  = fmaxf(mrow[i], mt);
            float alpha = __expf(mrow[i] - mnew);
            mrow[i] = mnew;

            float rs = 0.f;
            #pragma unroll
            for (int j = 0; j < 4; j++) {
                float p = __expf(s[i][j] - mnew);
                s[i][j] = p;
                rs += p;
            }
            rs += __shfl_xor_sync(0xffffffffu, rs, 8);
            rs += __shfl_xor_sync(0xffffffffu, rs, 4);
            rs += __shfl_xor_sync(0xffffffffu, rs, 2);
            rs += __shfl_xor_sync(0xffffffffu, rs, 1);

            lrow[i] = lrow[i] * alpha + rs;
            #pragma unroll
            for (int j = 0; j < 4; j++) o[i][j] *= alpha;
        }

        // ---- stage P transposed (stride 65 kills bank conflicts) ----
        #pragma unroll
        for (int i = 0; i < 4; i++)
            #pragma unroll
            for (int j = 0; j < 4; j++)
                Pt[(tx * 4 + j) * 65 + ty * 4 + i] = s[i][j];
        __syncthreads();

        // ---- O += P @ V ----
        #pragma unroll 8
        for (int c = 0; c < 64; c++) {
            float4 v = *(const float4*)(Vs + c * 64 + tx * 4);
            float vr[4] = {v.x, v.y, v.z, v.w};
            float pr[4];
            #pragma unroll
            for (int i = 0; i < 4; i++) pr[i] = Pt[c * 65 + ty * 4 + i];
            #pragma unroll
            for (int i = 0; i < 4; i++)
                #pragma unroll
                for (int j = 0; j < 4; j++)
                    o[i][j] += pr[i] * vr[j];
        }
    }

    // ---- normalize + write ctx in [B,S,D] layout ----
    const int b = bh / H_;
    const int h = bh - b * H_;
    #pragma unroll
    for (int i = 0; i < 4; i++) {
        float inv = 1.0f / lrow[i];
        int srow  = q0 + ty * 4 + i;
        float4 ov = make_float4(o[i][0] * inv, o[i][1] * inv,
                                o[i][2] * inv, o[i][3] * inv);
        *(float4*)(ctx + (size_t)(b * S_ + srow) * D_ + h * HD_ + tx * 4) = ov;
    }
}

// ---------------------------------------------------------------------------
extern "C" void kernel_launch(void* const* d_in, const int* in_sizes, int n_in,
                              void* d_out, int out_size)
{
    (void)in_sizes; (void)n_in; (void)out_size;
    const float* x  = (const float*)d_in[0];
    const float* wq = (const float*)d_in[1];
    const float* wk = (const float*)d_in[2];
    const float* wv = (const float*)d_in[3];
    const float* wo = (const float*)d_in[4];
    const float* bo = (const float*)d_in[5];
    float* out = (float*)d_out;

    float *q, *k, *v, *ctx;
    cudaGetSymbolAddress((void**)&q,   g_q);
    cudaGetSymbolAddress((void**)&k,   g_k);
    cudaGetSymbolAddress((void**)&v,   g_v);
    cudaGetSymbolAddress((void**)&ctx, g_ctx);

    dim3 gthreads(256);
    dim3 ggrid(D_ / 64, M_ / 64);   // (12, 128)

    gemm_kernel<0><<<ggrid, gthreads>>>(x, wq, nullptr, q, D_, D_);
    gemm_kernel<0><<<ggrid, gthreads>>>(x, wk, nullptr, k, D_, D_);
    gemm_kernel<0><<<ggrid, gthreads>>>(x, wv, nullptr, v, D_, D_);

    const int smem_bytes = (3 * 4096 + 64 * 65) * (int)sizeof(float); // 65792
    cudaFuncSetAttribute(flash_kernel,
                         cudaFuncAttributeMaxDynamicSharedMemorySize, smem_bytes);
    flash_kernel<<<dim3(S_ / 64, B_ * H_), gthreads, smem_bytes>>>(q, k, v, ctx);

    gemm_kernel<1><<<ggrid, gthreads>>>(ctx, wo, bo, out, D_, D_);
}